// round 4
// baseline (speedup 1.0000x reference)
#include <cuda_runtime.h>
#include <cuda_bf16.h>
#include <cstdint>

// DFT_10316511445664 — batched 100-pt DFT as mma.sync bf16 split GEMM, persistent
// tile-looping CTAs with cp.async prefetch.
// out[B,100] = x[B,100] @ W[100,100]; 3 K-segments: x_hi*W_hi + x_lo*W_hi + x_hi*W_lo.

#define NFFT  100
#define CROP  50
#define MT    64           // rows per tile
#define BT    256
#define KS7   7
#define GRID  444          // 148 SMs * 3 CTAs

// Precomputed B fragments in exact mma.m16n8k16 per-lane layout.
// [term(hi/lo)][ks][wn][nt][lane] -> {b0,b1}. Cols >= 100 are exact zeros.
__device__ uint2 g_bfrag[2][KS7][2][KS7][32];

__device__ __forceinline__ double wval(int k, int n) {
    if (k >= NFFT || n >= NFFT) return 0.0;
    const int j = (n < CROP) ? n : n - CROP;
    const int m = (k * j) % 100;
    double s, c;
    sincospi((double)(2 * m) / 100.0, &s, &c);
    double t = (n < CROP) ? c : -s;
    if (k & 1) t = -t;
    return t * 0.01;
}

__global__ void winit_kernel() {
    const int i = blockIdx.x * blockDim.x + threadIdx.x;
    if (i >= 2 * KS7 * 2 * KS7 * 32) return;
    const int lane = i & 31;
    int t1 = i >> 5;
    const int nt = t1 % 7;  t1 /= 7;
    const int wn = t1 & 1;  t1 >>= 1;
    const int ks = t1 % 7;
    const int term = t1 / 7;
    const int g = lane >> 2, tg = lane & 3;
    const int n = 56 * wn + 8 * nt + g;
    uint32_t v[2];
#pragma unroll
    for (int h = 0; h < 2; ++h) {
        uint32_t p = 0;
#pragma unroll
        for (int e = 0; e < 2; ++e) {
            const int k = ks * 16 + 2 * tg + 8 * h + e;
            const double w = wval(k, n);
            const __nv_bfloat16 bh = __float2bfloat16((float)w);
            const float fh = __bfloat162float(bh);
            const __nv_bfloat16 bl = __float2bfloat16((float)(w - (double)fh));
            const unsigned short u = (term == 0) ? __bfloat16_as_ushort(bh)
                                                 : __bfloat16_as_ushort(bl);
            p |= (uint32_t)u << (16 * e);
        }
        v[h] = p;
    }
    g_bfrag[term][ks][wn][nt][lane] = make_uint2(v[0], v[1]);
}

__device__ __forceinline__ void mma16816(uint32_t* d, const uint4& a, const uint2& b) {
    asm volatile(
        "mma.sync.aligned.m16n8k16.row.col.f32.bf16.bf16.f32 "
        "{%0,%1,%2,%3}, {%4,%5,%6,%7}, {%8,%9}, {%0,%1,%2,%3};"
        : "+r"(d[0]), "+r"(d[1]), "+r"(d[2]), "+r"(d[3])
        : "r"(a.x), "r"(a.y), "r"(a.z), "r"(a.w), "r"(b.x), "r"(b.y));
}

__device__ __forceinline__ uint32_t smem_u32(const void* p) {
    uint32_t a;
    asm("{ .reg .u64 t; cvta.to.shared.u64 t, %1; cvt.u32.u64 %0, t; }" : "=r"(a) : "l"(p));
    return a;
}
#define CP_ASYNC16(dst, src) \
    asm volatile("cp.async.cg.shared.global [%0], [%1], 16;" :: "r"(dst), "l"(src))
#define CP_COMMIT()  asm volatile("cp.async.commit_group;" ::: "memory")
#define CP_WAIT0()   asm volatile("cp.async.wait_group 0;" ::: "memory")

// smem layout
#define AF_SLOT(t, w, k, l) ((((t) * 4 + (w)) * KS7 + (k)) * 32 + (l))
#define AF_BYTES   (2 * 4 * KS7 * 32 * 16)        // 28672
#define RAW_OFF    AF_BYTES
#define RAW_BYTES  (MT * NFFT * 4)                // 25600
#define PS_OFF     (AF_BYTES + RAW_BYTES)         // 54272
#define SMEM_TOTAL (PS_OFF + MT * 2 * 4)          // 54784

__global__ __launch_bounds__(BT, 3) void dft_mma(const float* __restrict__ x,
                                                 float* __restrict__ xfft,
                                                 float* __restrict__ logp,
                                                 int ntiles) {
    extern __shared__ char smem[];
    uint4* const af         = reinterpret_cast<uint4*>(smem);
    const float2* const raw = reinterpret_cast<const float2*>(smem + RAW_OFF);
    float* const ps         = reinterpret_cast<float*>(smem + PS_OFF);
    const uint32_t raw_s    = smem_u32(smem + RAW_OFF);

    const int tid  = threadIdx.x;
    const int wid  = tid >> 5;
    const int lane = tid & 31;
    const int wm   = wid >> 1;
    const int wn   = wid & 1;
    const int g    = lane >> 2, tg = lane & 3;

    // Zero A-frag region once; K-padding slots (k=100..111) are never rewritten.
#pragma unroll
    for (int j = 0; j < 7; ++j) af[tid + j * BT] = make_uint4(0, 0, 0, 0);

    // Prefetch first tile's x
    {
        const char* src = reinterpret_cast<const char*>(x) + (size_t)blockIdx.x * RAW_BYTES;
#pragma unroll
        for (int j = 0; j < 7; ++j) {
            const int idx = tid + j * BT;
            if (idx < RAW_BYTES / 16) CP_ASYNC16(raw_s + idx * 16, src + idx * 16);
        }
        CP_COMMIT();
    }

    for (int tile = blockIdx.x; tile < ntiles; tile += GRID) {
        CP_WAIT0();
        __syncthreads();     // raw(t) ready; af free (mma reads of t-1 done)

        // Scatter: fp32 -> bf16 hi/lo split into fragment-linear smem slots.
#pragma unroll
        for (int j = 0; j < 13; ++j) {
            const int i = tid + j * BT;
            if (i < MT * CROP) {
                const float2 v = raw[i];
                const int r = i / CROP, c = i - r * CROP;
                uint32_t hi;
                asm("cvt.rn.bf16x2.f32 %0, %1, %2;" : "=r"(hi) : "f"(v.y), "f"(v.x));
                const float h0 = __uint_as_float(hi << 16);
                const float h1 = __uint_as_float(hi & 0xffff0000u);
                uint32_t lo;
                asm("cvt.rn.bf16x2.f32 %0, %1, %2;" : "=r"(lo) : "f"(v.y - h1), "f"(v.x - h0));
                const int wmr = r >> 4, row16 = r & 15;
                const int ks = c >> 3, cc = c & 7;
                const int reg = (row16 >> 3) | ((cc >> 2) << 1);
                const int ln  = (row16 & 7) * 4 + (cc & 3);
                reinterpret_cast<uint32_t*>(&af[AF_SLOT(0, wmr, ks, ln)])[reg] = hi;
                reinterpret_cast<uint32_t*>(&af[AF_SLOT(1, wmr, ks, ln)])[reg] = lo;
            }
        }
        __syncthreads();     // af ready; raw reusable

        // Prefetch next tile under the mma
        {
            const int next = tile + GRID;
            if (next < ntiles) {
                const char* src = reinterpret_cast<const char*>(x) + (size_t)next * RAW_BYTES;
#pragma unroll
                for (int j = 0; j < 7; ++j) {
                    const int idx = tid + j * BT;
                    if (idx < RAW_BYTES / 16) CP_ASYNC16(raw_s + idx * 16, src + idx * 16);
                }
            }
            CP_COMMIT();
        }

        // Mainloop: 3 segments x 7 ksteps; wn=1 skips all-zero nt=6 (cols 104..111).
        uint32_t acc[7][4];
#pragma unroll
        for (int nt = 0; nt < 7; ++nt)
#pragma unroll
            for (int q = 0; q < 4; ++q) acc[nt][q] = 0u;

#pragma unroll
        for (int seg = 0; seg < 3; ++seg) {
            const int at = (seg == 1) ? 1 : 0;
            const int bt = (seg == 2) ? 1 : 0;
#pragma unroll
            for (int ks = 0; ks < KS7; ++ks) {
                const uint4 a = af[AF_SLOT(at, wm, ks, lane)];
#pragma unroll
                for (int nt = 0; nt < 7; ++nt) {
                    if (nt == 6 && wn) break;
                    const uint2 b = g_bfrag[bt][ks][wn][nt][lane];
                    mma16816(acc[nt], a, b);
                }
            }
        }

        // Epilogue: direct float2 stores + fused |z|^2 partials.
        float s0 = 0.f, s1 = 0.f;
        float* const outb = xfft + (size_t)tile * (MT * NFFT);
        const int r0 = 16 * wm + g;
#pragma unroll
        for (int nt = 0; nt < 7; ++nt) {
            if (nt == 6 && wn) break;
            const int c0 = 56 * wn + 8 * nt + 2 * tg;
            const float f0 = __uint_as_float(acc[nt][0]);
            const float f1 = __uint_as_float(acc[nt][1]);
            const float f2 = __uint_as_float(acc[nt][2]);
            const float f3 = __uint_as_float(acc[nt][3]);
            s0 += f0 * f0 + f1 * f1;            // padded cols are exact zeros
            s1 += f2 * f2 + f3 * f3;
            if (c0 < NFFT) {
                *reinterpret_cast<float2*>(outb + (size_t)r0 * NFFT + c0)       = make_float2(f0, f1);
                *reinterpret_cast<float2*>(outb + (size_t)(r0 + 8) * NFFT + c0) = make_float2(f2, f3);
            }
        }
        s0 += __shfl_xor_sync(0xffffffffu, s0, 1);
        s0 += __shfl_xor_sync(0xffffffffu, s0, 2);
        s1 += __shfl_xor_sync(0xffffffffu, s1, 1);
        s1 += __shfl_xor_sync(0xffffffffu, s1, 2);
        if (tg == 0) {
            ps[2 * r0 + wn]       = s0;
            ps[2 * (r0 + 8) + wn] = s1;
        }
        __syncthreads();
        if (tid < MT)
            logp[(size_t)tile * MT + tid] =
                -0.5f * (ps[2 * tid] + ps[2 * tid + 1]) - 91.893853320467274f;
    }
}

extern "C" void kernel_launch(void* const* d_in, const int* in_sizes, int n_in,
                              void* d_out, int out_size) {
    const float* x = (const float*)d_in[0];
    const int B = in_sizes[0] / NFFT;              // 262144
    float* xf = (float*)d_out;
    float* lp = xf + (size_t)B * NFFT;
    static bool attr_set = false;
    if (!attr_set) {
        cudaFuncSetAttribute(dft_mma, cudaFuncAttributeMaxDynamicSharedMemorySize, SMEM_TOTAL);
        attr_set = true;
    }
    winit_kernel<<<(2 * KS7 * 2 * KS7 * 32 + 255) / 256, 256>>>();
    dft_mma<<<GRID, BT, SMEM_TOTAL>>>(x, xf, lp, B / MT);
}

// round 5
// speedup vs baseline: 2.6511x; 2.6511x over previous
#include <cuda_runtime.h>
#include <cuda_bf16.h>
#include <cstdint>

// DFT_10316511445664 — batched 100-pt DFT as mma.sync bf16 split GEMM.
// out[B,100] = x[B,100] @ W[100,100]; 3 terms: x_hi*W_hi + x_lo*W_hi + x_hi*W_lo.
// Barrier-free mainloop: A fragments loaded straight from gmem into registers
// (layout matches m16n8k16 lane ownership), hi/lo split in regs; B fragments in
// smem (loaded once per persistent CTA); warp tile m16 x n104 so log_pz reduces
// entirely in-warp.

#define NFFT  100
#define CROP  50
#define MT    128
#define BT    256
#define GRID  444        // 148 SMs * 3 CTAs
#define NKS   7
#define NNT   13

// Precomputed B fragments, exact m16n8k16 per-lane layout, hi/lo interleaved:
// [ks][nt][lane] -> {bhi0, bhi1, blo0, blo1}. Cols >= 100 are exact zeros.
__device__ uint4 g_bfrag[NKS][NNT][32];

__device__ __forceinline__ double wval(int k, int n) {
    if (k >= NFFT || n >= NFFT) return 0.0;
    const int j = (n < CROP) ? n : n - CROP;
    const int m = (k * j) % 100;
    double s, c;
    sincospi((double)(2 * m) / 100.0, &s, &c);
    double t = (n < CROP) ? c : -s;   // re: cos ; im: -sin
    if (k & 1) t = -t;                // fftshift (-1)^k
    return t * 0.01;                  // 1/N_FFT
}

__global__ void winit_kernel() {
    const int i = blockIdx.x * blockDim.x + threadIdx.x;
    if (i >= NKS * NNT * 32) return;
    const int lane = i & 31;
    const int t = i >> 5;
    const int nt = t % NNT, ks = t / NNT;
    const int g = lane >> 2, tg = lane & 3;
    const int n = 8 * nt + g;
    uint32_t vh[2], vl[2];
#pragma unroll
    for (int h = 0; h < 2; ++h) {
        uint32_t ph = 0, pl = 0;
#pragma unroll
        for (int e = 0; e < 2; ++e) {
            const int k = ks * 16 + 2 * tg + 8 * h + e;
            const double w = wval(k, n);
            const __nv_bfloat16 bh = __float2bfloat16((float)w);
            const float fh = __bfloat162float(bh);
            const __nv_bfloat16 bl = __float2bfloat16((float)(w - (double)fh));
            ph |= (uint32_t)__bfloat16_as_ushort(bh) << (16 * e);
            pl |= (uint32_t)__bfloat16_as_ushort(bl) << (16 * e);
        }
        vh[h] = ph; vl[h] = pl;
    }
    g_bfrag[ks][nt][lane] = make_uint4(vh[0], vh[1], vl[0], vl[1]);
}

__device__ __forceinline__ void mma16816(uint32_t* d, const uint4& a,
                                         uint32_t b0, uint32_t b1) {
    asm volatile(
        "mma.sync.aligned.m16n8k16.row.col.f32.bf16.bf16.f32 "
        "{%0,%1,%2,%3}, {%4,%5,%6,%7}, {%8,%9}, {%0,%1,%2,%3};"
        : "+r"(d[0]), "+r"(d[1]), "+r"(d[2]), "+r"(d[3])
        : "r"(a.x), "r"(a.y), "r"(a.z), "r"(a.w), "r"(b0), "r"(b1));
}

// split one float2 into bf16x2 hi + bf16x2 lo (lo = exact fp32 residual rounded)
__device__ __forceinline__ void split2(float2 v, uint32_t& hi, uint32_t& lo) {
    asm("cvt.rn.bf16x2.f32 %0, %1, %2;" : "=r"(hi) : "f"(v.y), "f"(v.x));
    const float h0 = __uint_as_float(hi << 16);
    const float h1 = __uint_as_float(hi & 0xffff0000u);
    asm("cvt.rn.bf16x2.f32 %0, %1, %2;" : "=r"(lo) : "f"(v.y - h1), "f"(v.x - h0));
}

__global__ __launch_bounds__(BT, 3) void dft_mma(const float* __restrict__ x,
                                                 float* __restrict__ xfft,
                                                 float* __restrict__ logp,
                                                 int ntiles) {
    __shared__ uint4 bsh[NKS][NNT][32];

    const int tid  = threadIdx.x;
    const int wid  = tid >> 5;
    const int lane = tid & 31;
    const int g    = lane >> 2, tg = lane & 3;

    // Load B fragments into smem once per persistent CTA.
    {
        const uint4* gb = &g_bfrag[0][0][0];
        uint4* sb = &bsh[0][0][0];
        for (int i = tid; i < NKS * NNT * 32; i += BT) sb[i] = gb[i];
    }
    __syncthreads();

    for (int tile = blockIdx.x; tile < ntiles; tile += GRID) {
        const int r0 = tile * MT + wid * 16 + g;     // this lane's base row
        const float* const xr = x + (size_t)r0 * NFFT;

        uint32_t acc[NNT][4];
#pragma unroll
        for (int nt = 0; nt < NNT; ++nt)
#pragma unroll
            for (int q = 0; q < 4; ++q) acc[nt][q] = 0u;

#pragma unroll
        for (int ks = 0; ks < NKS; ++ks) {
            const int c0 = ks * 16 + 2 * tg;
            const bool v0 = (c0 < NFFT);             // false only ks=6, tg>=2
            const bool v1 = (c0 + 8 < NFFT);         // false for all of ks=6
            const float2 z2 = make_float2(0.f, 0.f);
            const float2 p00 = v0 ? *reinterpret_cast<const float2*>(xr + c0) : z2;
            const float2 p01 = v0 ? *reinterpret_cast<const float2*>(xr + 8 * NFFT + c0) : z2;
            const float2 p10 = v1 ? *reinterpret_cast<const float2*>(xr + c0 + 8) : z2;
            const float2 p11 = v1 ? *reinterpret_cast<const float2*>(xr + 8 * NFFT + c0 + 8) : z2;

            uint4 ahi, alo;
            split2(p00, ahi.x, alo.x);
            split2(p01, ahi.y, alo.y);
            split2(p10, ahi.z, alo.z);
            split2(p11, ahi.w, alo.w);

#pragma unroll
            for (int nt = 0; nt < NNT; ++nt) {
                const uint4 b = bsh[ks][nt][lane];
                mma16816(acc[nt], ahi, b.x, b.y);    // x_hi * W_hi
                mma16816(acc[nt], alo, b.x, b.y);    // x_lo * W_hi
                mma16816(acc[nt], ahi, b.z, b.w);    // x_hi * W_lo
            }
        }

        // Epilogue: coalesced float2 stores + fused |z|^2 (padded cols exact 0).
        float s0 = 0.f, s1 = 0.f;
        float* const outr = xfft + (size_t)r0 * NFFT;
#pragma unroll
        for (int nt = 0; nt < NNT; ++nt) {
            const int c0 = 8 * nt + 2 * tg;
            const float f0 = __uint_as_float(acc[nt][0]);
            const float f1 = __uint_as_float(acc[nt][1]);
            const float f2 = __uint_as_float(acc[nt][2]);
            const float f3 = __uint_as_float(acc[nt][3]);
            s0 += f0 * f0 + f1 * f1;
            s1 += f2 * f2 + f3 * f3;
            if (c0 < NFFT) {
                *reinterpret_cast<float2*>(outr + c0)            = make_float2(f0, f1);
                *reinterpret_cast<float2*>(outr + 8 * NFFT + c0) = make_float2(f2, f3);
            }
        }
        // Row sums live across the 4 tg lanes of each group: butterfly over tg.
        s0 += __shfl_xor_sync(0xffffffffu, s0, 1);
        s0 += __shfl_xor_sync(0xffffffffu, s0, 2);
        s1 += __shfl_xor_sync(0xffffffffu, s1, 1);
        s1 += __shfl_xor_sync(0xffffffffu, s1, 2);
        if (tg == 0) {
            logp[r0]     = -0.5f * s0 - 91.893853320467274f;
            logp[r0 + 8] = -0.5f * s1 - 91.893853320467274f;
        }
    }
}

extern "C" void kernel_launch(void* const* d_in, const int* in_sizes, int n_in,
                              void* d_out, int out_size) {
    const float* x = (const float*)d_in[0];
    const int B = in_sizes[0] / NFFT;              // 262144
    float* xf = (float*)d_out;
    float* lp = xf + (size_t)B * NFFT;
    winit_kernel<<<(NKS * NNT * 32 + 255) / 256, 256>>>();
    dft_mma<<<GRID, BT>>>(x, xf, lp, B / MT);
}

// round 6
// speedup vs baseline: 3.1580x; 1.1912x over previous
#include <cuda_runtime.h>
#include <cuda_fp16.h>
#include <cstdint>

// DFT_10316511445664 — batched 100-pt DFT as mma.sync fp16 2-term split GEMM.
// out[B,100] = x[B,100] @ W[100,100]; terms: x_hi*W + x_lo*W (x_hi+x_lo == x to
// ~2^-22; W rounded once to fp16 -> norm rel err ~1.4e-4, tolerance 1e-3).
// Barrier-free persistent mainloop: A fragments loaded straight from gmem into
// registers (m16n8k16 lane ownership), hi/lo split in regs; B fragments in smem
// (loaded once per CTA, LDS.64); warp tile m16 x n104, log_pz reduced in-warp.

#define NFFT  100
#define CROP  50
#define MT    128
#define BT    256
#define GRID  444        // 148 SMs * 3 CTAs
#define NKS   7
#define NNT   13

// Precomputed B fragments, exact m16n8k16 per-lane layout (fp16):
// [ks][nt][lane] -> {b0, b1}. Cols >= 100 are exact zeros.
__device__ uint2 g_bfrag[NKS][NNT][32];

__device__ __forceinline__ double wval(int k, int n) {
    if (k >= NFFT || n >= NFFT) return 0.0;
    const int j = (n < CROP) ? n : n - CROP;
    const int m = (k * j) % 100;
    double s, c;
    sincospi((double)(2 * m) / 100.0, &s, &c);
    double t = (n < CROP) ? c : -s;   // re: cos ; im: -sin
    if (k & 1) t = -t;                // fftshift (-1)^k
    return t * 0.01;                  // 1/N_FFT
}

__global__ void winit_kernel() {
    const int i = blockIdx.x * blockDim.x + threadIdx.x;
    if (i >= NKS * NNT * 32) return;
    const int lane = i & 31;
    const int t = i >> 5;
    const int nt = t % NNT, ks = t / NNT;
    const int g = lane >> 2, tg = lane & 3;
    const int n = 8 * nt + g;
    uint32_t v[2];
#pragma unroll
    for (int h = 0; h < 2; ++h) {
        uint32_t p = 0;
#pragma unroll
        for (int e = 0; e < 2; ++e) {
            const int k = ks * 16 + 2 * tg + 8 * h + e;
            const __half w = __float2half_rn((float)wval(k, n));
            p |= (uint32_t)__half_as_ushort(w) << (16 * e);
        }
        v[h] = p;
    }
    g_bfrag[ks][nt][lane] = make_uint2(v[0], v[1]);
}

__device__ __forceinline__ void mma16816(uint32_t* d, const uint4& a,
                                         uint32_t b0, uint32_t b1) {
    asm volatile(
        "mma.sync.aligned.m16n8k16.row.col.f32.f16.f16.f32 "
        "{%0,%1,%2,%3}, {%4,%5,%6,%7}, {%8,%9}, {%0,%1,%2,%3};"
        : "+r"(d[0]), "+r"(d[1]), "+r"(d[2]), "+r"(d[3])
        : "r"(a.x), "r"(a.y), "r"(a.z), "r"(a.w), "r"(b0), "r"(b1));
}

// split float2 -> fp16x2 hi + fp16x2 lo (lo = rounded fp32 residual; x = hi+lo
// to ~2^-22 relative). Low 16 bits hold the even-k (v.x) element.
__device__ __forceinline__ void split2(float2 v, uint32_t& hi, uint32_t& lo) {
    asm("cvt.rn.f16x2.f32 %0, %1, %2;" : "=r"(hi) : "f"(v.y), "f"(v.x));
    float h0, h1;
    asm("{ .reg .b16 a, b; mov.b32 {a, b}, %2; cvt.f32.f16 %0, a; cvt.f32.f16 %1, b; }"
        : "=f"(h0), "=f"(h1) : "r"(hi));
    asm("cvt.rn.f16x2.f32 %0, %1, %2;" : "=r"(lo) : "f"(v.y - h1), "f"(v.x - h0));
}

__global__ __launch_bounds__(BT, 3) void dft_mma(const float* __restrict__ x,
                                                 float* __restrict__ xfft,
                                                 float* __restrict__ logp,
                                                 int ntiles) {
    __shared__ uint2 bsh[NKS][NNT][32];

    const int tid  = threadIdx.x;
    const int wid  = tid >> 5;
    const int lane = tid & 31;
    const int g    = lane >> 2, tg = lane & 3;

    // Load B fragments into smem once per persistent CTA.
    {
        const uint2* gb = &g_bfrag[0][0][0];
        uint2* sb = &bsh[0][0][0];
        for (int i = tid; i < NKS * NNT * 32; i += BT) sb[i] = gb[i];
    }
    __syncthreads();

    for (int tile = blockIdx.x; tile < ntiles; tile += GRID) {
        const int r0 = tile * MT + wid * 16 + g;     // this lane's base row
        const float* const xr = x + (size_t)r0 * NFFT;

        uint32_t acc[NNT][4];
#pragma unroll
        for (int nt = 0; nt < NNT; ++nt)
#pragma unroll
            for (int q = 0; q < 4; ++q) acc[nt][q] = 0u;

#pragma unroll
        for (int ks = 0; ks < NKS; ++ks) {
            const int c0 = ks * 16 + 2 * tg;
            const bool v0 = (c0 < NFFT);             // false only ks=6, tg>=2
            const bool v1 = (c0 + 8 < NFFT);         // false for all of ks=6
            const float2 z2 = make_float2(0.f, 0.f);
            const float2 p00 = v0 ? *reinterpret_cast<const float2*>(xr + c0) : z2;
            const float2 p01 = v0 ? *reinterpret_cast<const float2*>(xr + 8 * NFFT + c0) : z2;
            const float2 p10 = v1 ? *reinterpret_cast<const float2*>(xr + c0 + 8) : z2;
            const float2 p11 = v1 ? *reinterpret_cast<const float2*>(xr + 8 * NFFT + c0 + 8) : z2;

            uint4 ahi, alo;
            split2(p00, ahi.x, alo.x);
            split2(p01, ahi.y, alo.y);
            split2(p10, ahi.z, alo.z);
            split2(p11, ahi.w, alo.w);

#pragma unroll
            for (int nt = 0; nt < NNT; ++nt) {
                const uint2 b = bsh[ks][nt][lane];
                mma16816(acc[nt], ahi, b.x, b.y);    // x_hi * W
                mma16816(acc[nt], alo, b.x, b.y);    // x_lo * W
            }
        }

        // Epilogue: coalesced float2 stores + fused |z|^2 (padded cols exact 0).
        float s0 = 0.f, s1 = 0.f;
        float* const outr = xfft + (size_t)r0 * NFFT;
#pragma unroll
        for (int nt = 0; nt < NNT; ++nt) {
            const int c0 = 8 * nt + 2 * tg;
            const float f0 = __uint_as_float(acc[nt][0]);
            const float f1 = __uint_as_float(acc[nt][1]);
            const float f2 = __uint_as_float(acc[nt][2]);
            const float f3 = __uint_as_float(acc[nt][3]);
            s0 += f0 * f0 + f1 * f1;
            s1 += f2 * f2 + f3 * f3;
            if (c0 < NFFT) {
                *reinterpret_cast<float2*>(outr + c0)            = make_float2(f0, f1);
                *reinterpret_cast<float2*>(outr + 8 * NFFT + c0) = make_float2(f2, f3);
            }
        }
        // Row sums live across the 4 tg lanes of each group: butterfly over tg.
        s0 += __shfl_xor_sync(0xffffffffu, s0, 1);
        s0 += __shfl_xor_sync(0xffffffffu, s0, 2);
        s1 += __shfl_xor_sync(0xffffffffu, s1, 1);
        s1 += __shfl_xor_sync(0xffffffffu, s1, 2);
        if (tg == 0) {
            logp[r0]     = -0.5f * s0 - 91.893853320467274f;
            logp[r0 + 8] = -0.5f * s1 - 91.893853320467274f;
        }
    }
}

extern "C" void kernel_launch(void* const* d_in, const int* in_sizes, int n_in,
                              void* d_out, int out_size) {
    const float* x = (const float*)d_in[0];
    const int B = in_sizes[0] / NFFT;              // 262144
    float* xf = (float*)d_out;
    float* lp = xf + (size_t)B * NFFT;
    winit_kernel<<<(NKS * NNT * 32 + 255) / 256, 256>>>();
    dft_mma<<<GRID, BT>>>(x, xf, lp, B / MT);
}